// round 11
// baseline (speedup 1.0000x reference)
#include <cuda_runtime.h>
#include <cuda_bf16.h>
#include <math.h>
#include <stdint.h>

#define Ln 128
#define Bn 4096
#define Dn 300
#define XROW 624                // 304 bf16 + 16B pad (stride/16 odd -> conflict-free)
#define MT 64                   // rows per CTA
#define SM_X  0
#define SM_RA 39936             // 64*624
#define SM_RC 40960
#define DYN_SMEM 41984

// Fragment-ordered B image: blob (ch,ks,wn) of [lane][12 u32] (10 real + 2 pad).
// u32 (s,half): bf16 pair Ws[k0][n],Ws[k0+1][n]; n = ch*160+wn*40+8s+g, k0 = ks*16+half*8+2q.
#define NBLOB (2*19*4)
__device__ __align__(16) uint32_t g_Wfrag[NBLOB * 32 * 12];
__device__ float g_A[Ln * Bn];
__device__ float g_C[Ln * Bn];

__device__ __forceinline__ uint32_t smem_to_u32(const void* p) {
    uint32_t a;
    asm("{ .reg .u64 t; cvta.to.shared.u64 t, %1; cvt.u32.u64 %0, t; }" : "=r"(a) : "l"(p));
    return a;
}

#define LDSM_X4(r, addr)                                                        \
    asm volatile("ldmatrix.sync.aligned.m8n8.x4.shared.b16 {%0,%1,%2,%3}, [%4];"\
        : "=r"((r)[0]),"=r"((r)[1]),"=r"((r)[2]),"=r"((r)[3]) : "r"(addr))
#define MMA16816(d, a, b0, b1)                                                  \
    asm volatile("mma.sync.aligned.m16n8k16.row.col.f32.bf16.bf16.f32 "         \
        "{%0,%1,%2,%3}, {%4,%5,%6,%7}, {%8,%9}, {%0,%1,%2,%3};"                 \
        : "+f"((d)[0]),"+f"((d)[1]),"+f"((d)[2]),"+f"((d)[3])                   \
        : "r"((a)[0]),"r"((a)[1]),"r"((a)[2]),"r"((a)[3]), "r"(b0),"r"(b1))

// ============ kernel 1: build fragment-ordered bf16 Ws image ============
__global__ void prepW_kernel(const float* __restrict__ W) {
    int idx = blockIdx.x * 256 + threadIdx.x;
    if (idx >= NBLOB * 32 * 12) return;
    int su   = idx % 12;
    int lane = (idx / 12) & 31;
    int blob = idx / (32 * 12);
    int wn = blob & 3, ks = (blob >> 2) % 19, ch = blob / 76;
    int g = lane >> 2, q = lane & 3;
    uint32_t pk = 0u;
    if (su < 10) {
        int s = su >> 1, half = su & 1;
        int n  = ch * 160 + wn * 40 + 8 * s + g;
        int k0 = ks * 16 + half * 8 + 2 * q;
        float v0 = 0.f, v1 = 0.f;
        if (n < Dn) {
            if (k0 < Dn)     v0 = W[k0 * Dn + n] + W[n * Dn + k0];
            if (k0 + 1 < Dn) v1 = W[(k0 + 1) * Dn + n] + W[n * Dn + k0 + 1];
        }
        __nv_bfloat162 p = __floats2bfloat162_rn(v0, v1);
        pk = *(uint32_t*)&p;
    }
    g_Wfrag[idx] = pk;
}

// ============ kernel 2: M=64 HMMA GEMM (B fragments from L1/L2) + fused dots ============
__global__ __launch_bounds__(256, 3) void score_kernel(const float* __restrict__ S) {
    extern __shared__ __align__(16) char smem[];
    const uint32_t sb = smem_to_u32(smem);
    const int tid  = threadIdx.x;
    const int lane = tid & 31;
    const int wid  = tid >> 5;
    const int wm   = wid >> 2;           // 0..1 -> 32-row slice
    const int wn   = wid & 3;            // 0..3 -> 40-col slice within chunk
    const int r0   = 32 * wm;
    const int g    = lane >> 2, q = lane & 3;
    const int  tile = blockIdx.x;        // 0..8191
    const size_t m0 = (size_t)tile * MT;
    const bool hasPrev = (tile >= 64);

    // ---- stage X tile: 64 rows x 300 fp32 -> bf16 (cols 300..311 zero) ----
    const float* Sl = S + m0 * Dn;
    for (int idx = tid; idx < MT * 75; idx += 256) {
        int r = idx / 75, f = idx % 75;
        float4 v = __ldg((const float4*)(Sl + (size_t)r * Dn) + f);
        __nv_bfloat162 p0 = __floats2bfloat162_rn(v.x, v.y);
        __nv_bfloat162 p1 = __floats2bfloat162_rn(v.z, v.w);
        *(uint2*)(smem + SM_X + r * XROW + f * 8) =
            make_uint2(*(uint32_t*)&p0, *(uint32_t*)&p1);
    }
    for (int idx = tid; idx < MT * 3; idx += 256) {
        int r = idx / 3, w = idx % 3;
        *(uint2*)(smem + SM_X + r * XROW + 600 + w * 8) = make_uint2(0u, 0u);
    }
    __syncthreads();

    const uint32_t aBase0 = sb + SM_X + (r0 + (lane & 15)) * XROW + (lane >> 4) * 16;
    const uint32_t aBase1 = aBase0 + 16 * XROW;

    float aA[2] = {0.f, 0.f};            // [t] halves merged: [t][h] kept below
    float aB[2] = {0.f, 0.f};
    float cAa[2] = {0.f, 0.f};
    float cAb[2] = {0.f, 0.f};

    #pragma unroll
    for (int ch = 0; ch < 2; ch++) {
        // lane's fragment stream for this (ch, wn): 48B per ks
        const uint32_t* bp = g_Wfrag + ((size_t)((ch * 19) * 4 + wn) * 32 + lane) * 12;

        float acc[2][5][4];
        #pragma unroll
        for (int t = 0; t < 2; t++)
            #pragma unroll
            for (int s = 0; s < 5; s++)
                #pragma unroll
                for (int i = 0; i < 4; i++) acc[t][s][i] = 0.f;

        #pragma unroll 1
        for (int ks = 0; ks < 19; ks++) {
            uint32_t a0[4], a1[4];
            LDSM_X4(a0, aBase0 + ks * 32);
            LDSM_X4(a1, aBase1 + ks * 32);
            uint32_t bw[10];
            {
                uint4 v0 = __ldg((const uint4*)bp);
                uint4 v1 = __ldg((const uint4*)bp + 1);
                uint2 v2 = __ldg((const uint2*)(bp + 8));
                bw[0]=v0.x; bw[1]=v0.y; bw[2]=v0.z; bw[3]=v0.w;
                bw[4]=v1.x; bw[5]=v1.y; bw[6]=v1.z; bw[7]=v1.w;
                bw[8]=v2.x; bw[9]=v2.y;
            }
            bp += (size_t)4 * 32 * 12;   // next ks
            #pragma unroll
            for (int s = 0; s < 5; s++) {
                MMA16816(acc[0][s], a0, bw[2 * s], bw[2 * s + 1]);
                MMA16816(acc[1][s], a1, bw[2 * s], bw[2 * s + 1]);
            }
        }

        // ---- dot epilogue: self from X smem, prev from gmem (L2-hot) ----
        #pragma unroll
        for (int t = 0; t < 2; t++) {
            const int rowA = r0 + 16 * t + g;
            const int rowB = rowA + 8;
            const float* pA = S + (m0 + rowA - (size_t)Bn) * Dn;
            const float* pB = S + (m0 + rowB - (size_t)Bn) * Dn;
            float sa = 0.f, sbv = 0.f, ca = 0.f, cb = 0.f;
            #pragma unroll
            for (int s = 0; s < 5; s++) {
                const int colg = ch * 160 + wn * 40 + 8 * s + 2 * q;
                if (colg < 304) {        // beyond: acc==0 but smem unstaged (NaN x 0 = NaN)
                    uint32_t svA = *(const uint32_t*)(smem + SM_X + rowA * XROW + colg * 2);
                    uint32_t svB = *(const uint32_t*)(smem + SM_X + rowB * XROW + colg * 2);
                    __nv_bfloat162 sA2 = *(__nv_bfloat162*)&svA;
                    __nv_bfloat162 sB2 = *(__nv_bfloat162*)&svB;
                    sa  = fmaf(__bfloat162float(sA2.x), acc[t][s][0],
                          fmaf(__bfloat162float(sA2.y), acc[t][s][1], sa));
                    sbv = fmaf(__bfloat162float(sB2.x), acc[t][s][2],
                          fmaf(__bfloat162float(sB2.y), acc[t][s][3], sbv));
                    if (hasPrev && colg < Dn) {
                        float2 pvA = __ldg((const float2*)(pA + colg));
                        float2 pvB = __ldg((const float2*)(pB + colg));
                        ca = fmaf(pvA.x, acc[t][s][0], fmaf(pvA.y, acc[t][s][1], ca));
                        cb = fmaf(pvB.x, acc[t][s][2], fmaf(pvB.y, acc[t][s][3], cb));
                    }
                }
            }
            aA[t] += sa; aB[t] += sbv; cAa[t] += ca; cAb[t] += cb;
        }
    }

    // ---- reduce: q lanes, then the 4 wn-warps via smem ----
    float* sRA = (float*)(smem + SM_RA);   // [4][64]
    float* sRC = (float*)(smem + SM_RC);   // [4][64]
    #pragma unroll
    for (int t = 0; t < 2; t++)
        #pragma unroll
        for (int h = 0; h < 2; h++) {
            float a = h ? aB[t] : aA[t];
            float c = h ? cAb[t] : cAa[t];
            a += __shfl_xor_sync(0xffffffffu, a, 1);
            a += __shfl_xor_sync(0xffffffffu, a, 2);
            c += __shfl_xor_sync(0xffffffffu, c, 1);
            c += __shfl_xor_sync(0xffffffffu, c, 2);
            if (q == 0) {
                int row = r0 + 16 * t + 8 * h + g;
                sRA[wn * MT + row] = a;
                sRC[wn * MT + row] = c;
            }
        }
    __syncthreads();
    if (tid < MT) {
        float a = sRA[tid] + sRA[MT + tid] + sRA[2 * MT + tid] + sRA[3 * MT + tid];
        g_A[m0 + tid] = 0.5f * a;
        if (hasPrev) {
            float c = sRC[tid] + sRC[MT + tid] + sRC[2 * MT + tid] + sRC[3 * MT + tid];
            g_C[m0 + tid] = 0.5f * c;
        }
    }
}

// ============ kernel 3: l-streaming blend (R9 version) ============
__global__ __launch_bounds__(256) void blend_kernel(const float* __restrict__ S,
                                                    const int* __restrict__ sizes,
                                                    float* __restrict__ out) {
    const int warp = threadIdx.x >> 5;
    const int lane = threadIdx.x & 31;
    const int b    = blockIdx.x * 8 + warp;
    const int sz   = sizes[b];
    const float inv_d = 1.0f / 300.0f;

    bool val[3];
    #pragma unroll
    for (int j = 0; j < 3; j++) val[j] = (j * 32 + lane) < 75;

    const size_t slabF4 = (size_t)Bn * Dn / 4;        // 307200
    const float4* rp = (const float4*)(S + (size_t)b * Dn);
    float4*       op = (float4*)(out + (size_t)b * Dn);

    const float4 z = make_float4(0.f, 0.f, 0.f, 0.f);
    float4 prv[3] = {z, z, z}, cur[3], nxt[3];
    #pragma unroll
    for (int j = 0; j < 3; j++) cur[j] = val[j] ? __ldg(rp + j * 32 + lane) : z;

    for (int l = 0; l < Ln; ++l) {
        const bool hasN = (l < Ln - 1);
        #pragma unroll
        for (int j = 0; j < 3; j++)
            nxt[j] = (hasN && val[j]) ? __ldg(rp + slabF4 + j * 32 + lane) : z;

        float l1 = g_A[l * Bn + b] * inv_d;
        float l0 = (l >= 1 && l < sz)     ? g_C[l * Bn + b] * inv_d       : -INFINITY;
        float l2 = (hasN && l < sz - 1)   ? g_C[(l + 1) * Bn + b] * inv_d : -INFINITY;

        float mx = fmaxf(l1, fmaxf(l0, l2));
        float e0 = expf(l0 - mx), e1 = expf(l1 - mx), e2 = expf(l2 - mx);
        float inv = 1.0f / (e0 + e1 + e2);
        float w0 = e0 * inv, w1 = e1 * inv, w2 = e2 * inv;

        #pragma unroll
        for (int j = 0; j < 3; j++) {
            if (val[j]) {
                float4 r;
                r.x = w1 * cur[j].x + w0 * prv[j].x + w2 * nxt[j].x;
                r.y = w1 * cur[j].y + w0 * prv[j].y + w2 * nxt[j].y;
                r.z = w1 * cur[j].z + w0 * prv[j].z + w2 * nxt[j].z;
                r.w = w1 * cur[j].w + w0 * prv[j].w + w2 * nxt[j].w;
                op[j * 32 + lane] = r;
            }
        }
        #pragma unroll
        for (int j = 0; j < 3; j++) { prv[j] = cur[j]; cur[j] = nxt[j]; }
        rp += slabF4;
        op += slabF4;
    }
}

// ==================== launch ====================
extern "C" void kernel_launch(void* const* d_in, const int* in_sizes, int n_in,
                              void* d_out, int out_size) {
    const float* S     = (const float*)d_in[0];
    const int*   sizes = (const int*)d_in[1];
    const float* W     = (const float*)d_in[2];
    float*       out   = (float*)d_out;
    (void)in_sizes; (void)n_in; (void)out_size;

    prepW_kernel<<<(NBLOB * 32 * 12 + 255) / 256, 256>>>(W);

    cudaFuncSetAttribute(score_kernel, cudaFuncAttributeMaxDynamicSharedMemorySize, DYN_SMEM);
    score_kernel<<<8192, 256, DYN_SMEM>>>(S);

    blend_kernel<<<Bn / 8, 256>>>(S, sizes, out);
}